// round 11
// baseline (speedup 1.0000x reference)
#include <cuda_runtime.h>
#include <cuda_bf16.h>
#include <cstdint>

// out = relu(h @ W1[0:64,:] + b1) @ W2[0:64,:] + b2   (edge weights hardcoded 0)
// Warp-level bf16 split-precision HMMA (mma.sync m16n8k16), fp32 accumulate.
// D = Ahi*Bhi + Ahi*Blo + Alo*Bhi. Layer-1 C-frag == layer-2 A-frag layout.
// DUAL-SLAB (32 rows/warp), 1 pair/warp, grid=391 (R9 structure).
// NEW: each warp cp.asyncs its own 32x64f h tile into private smem at entry;
// DRAM latency hides under weight staging; A reads become conflict-free LDS.64
// (row pitch 288B: 72 words == 8 mod 32 -> distinct even banks per half-warp).

#define TPB   256

// ---- dynamic smem layout (bytes) ----
#define OFF_W1H  0
#define OFF_W1L  8192
#define OFF_W2H  16384
#define OFF_W2L  24576
#define OFF_B1   32768
#define OFF_B2   33024
#define OFF_TILE 33152
#define TILE_PITCH   288                       // bytes per row (256 data + 32 pad)
#define TILE_PER_W   (32 * TILE_PITCH)         // 9216 B per warp
#define SMEM_TOTAL   (OFF_TILE + 8 * TILE_PER_W)   // 106880 B (~104.4 KB)

#define SWZ(o) ((uint32_t)(o) ^ ((((uint32_t)(o)) >> 3) & 0x70))

__device__ __forceinline__ uint32_t smem_u32(const void* p) {
    uint32_t a;
    asm("{ .reg .u64 t; cvta.to.shared.u64 t, %1; cvt.u32.u64 %0, t; }" : "=r"(a) : "l"(p));
    return a;
}

__device__ __forceinline__ void cp_async16(uint32_t dst, const void* src) {
    asm volatile("cp.async.cg.shared.global [%0], [%1], 16;"
                 :: "r"(dst), "l"(src) : "memory");
}

__device__ __forceinline__ void ldsm_x4_t(uint32_t& r0, uint32_t& r1, uint32_t& r2, uint32_t& r3,
                                          uint32_t addr) {
    asm volatile("ldmatrix.sync.aligned.m8n8.x4.trans.shared.b16 {%0,%1,%2,%3}, [%4];"
                 : "=r"(r0), "=r"(r1), "=r"(r2), "=r"(r3) : "r"(addr));
}

__device__ __forceinline__ void mma16816(float* c, const uint32_t* a, uint32_t b0, uint32_t b1) {
    asm volatile(
        "mma.sync.aligned.m16n8k16.row.col.f32.bf16.bf16.f32 "
        "{%0,%1,%2,%3}, {%4,%5,%6,%7}, {%8,%9}, {%0,%1,%2,%3};"
        : "+f"(c[0]), "+f"(c[1]), "+f"(c[2]), "+f"(c[3])
        : "r"(a[0]), "r"(a[1]), "r"(a[2]), "r"(a[3]), "r"(b0), "r"(b1));
}

// split float2 {even k, odd k} -> packed hi bf16x2 / lo bf16x2.
__device__ __forceinline__ void split2(float2 v, uint32_t& hi, uint32_t& lo) {
    uint32_t hp;
    asm("cvt.rn.bf16x2.f32 %0, %1, %2;" : "=r"(hp) : "f"(v.y), "f"(v.x));  // lo half = v.x
    const float h0 = __uint_as_float(hp << 16);
    const float h1 = __uint_as_float(hp & 0xFFFF0000u);
    const float l0 = v.x - h0;
    const float l1 = v.y - h1;
    uint32_t lp;
    asm("cvt.rn.bf16x2.f32 %0, %1, %2;" : "=r"(lp) : "f"(l1), "f"(l0));
    hi = hp; lo = lp;
}
__device__ __forceinline__ void split4(float4 v, uint32_t& h0, uint32_t& h1,
                                       uint32_t& l0, uint32_t& l1) {
    split2(make_float2(v.x, v.y), h0, l0);
    split2(make_float2(v.z, v.w), h1, l1);
}

__global__ __launch_bounds__(TPB, 2)
void mlp_hmma_kernel(const float* __restrict__ h,
                     const float* __restrict__ W1,   // (128,64), rows 0..63 used
                     const float* __restrict__ b1,   // (64,)
                     const float* __restrict__ W2,   // (128,32), rows 0..63 used
                     const float* __restrict__ b2,   // (32,)
                     float* __restrict__ out,        // (N,32)
                     int N)
{
    extern __shared__ __align__(1024) char smem[];

    const int tid = threadIdx.x;
    const int wid = tid >> 5;
    const int lid = tid & 31;

    const int pair = blockIdx.x * (TPB / 32) + wid;   // 32 rows per warp
    const int row0 = pair * 32;

    // ---- 1) cp.async prefetch of this warp's 32x64f h tile (lane = row) ----
    const uint32_t sbase  = smem_u32(smem);
    const uint32_t myTile = sbase + OFF_TILE + wid * TILE_PER_W;
    {
        int r = row0 + lid;
        if (r >= N) r = N - 1;                        // clamped; compute is guarded
        const char* src = (const char*)(h + (size_t)r * 64);
        const uint32_t dst = myTile + lid * TILE_PITCH;
        #pragma unroll
        for (int c = 0; c < 16; ++c)
            cp_async16(dst + c * 16, src + c * 16);
        asm volatile("cp.async.commit_group;" ::: "memory");
    }

    // ---- 2) weight staging (hides the tile fetch): float4 loads, uint2 stores ----
    {
        const float4* __restrict__ W1v = (const float4*)W1;   // 1024 float4
        #pragma unroll
        for (int j = 0; j < 4; ++j) {
            const int idx = tid + j * TPB;
            const int k = idx >> 4, n4 = (idx & 15) << 2;
            uint32_t h0, h1, l0, l1; split4(W1v[idx], h0, h1, l0, l1);
            const uint32_t sw = SWZ(k * 128 + n4 * 2);
            *(uint2*)(smem + OFF_W1H + sw) = make_uint2(h0, h1);
            *(uint2*)(smem + OFF_W1L + sw) = make_uint2(l0, l1);
        }
        const float4* __restrict__ W2v = (const float4*)W2;   // 512 float4
        #pragma unroll
        for (int j = 0; j < 2; ++j) {
            const int idx = tid + j * TPB;
            const int k = idx >> 3, n4 = (idx & 7) << 2;
            uint32_t h0, h1, l0, l1; split4(W2v[idx], h0, h1, l0, l1);
            const uint32_t sw = SWZ(k * 128 + n4 * 2);
            *(uint2*)(smem + OFF_W2H + sw) = make_uint2(h0, h1);
            *(uint2*)(smem + OFF_W2L + sw) = make_uint2(l0, l1);
        }
    }
    if (tid < 64) ((float*)(smem + OFF_B1))[tid] = b1[tid];
    if (tid < 32) ((float*)(smem + OFF_B2))[tid] = b2[tid];

    asm volatile("cp.async.wait_group 0;" ::: "memory");
    __syncthreads();                                   // weights + cross-lane tile vis

    if (row0 >= N) return;

    const int g = lid >> 2;        // row group 0..7
    const int t = lid & 3;         // col pair 0..3

    // per-lane ldmatrix source geometry
    const int lm = lid >> 3, lr = lid & 7;
    const int kr = ((lm & 1) << 3) + lr;    // k row within 16-row k-step (0..15)
    const int nc = (lm >> 1) << 3;          // n offset within 16-col n-group (0 or 8)

    // SWZ(2048s + 128kr + 32jj + 2nc) = (u ^ (m&0x10)) + ((2048s+32jj) ^ (m&0x60))
    const uint32_t mask  = (uint32_t)((kr & 7) << 4);
    const uint32_t ubase = (uint32_t)(128 * kr + 2 * nc) ^ (mask & 0x10u);
    const uint32_t m56   = mask & 0x60u;
    const uint32_t a1h = sbase + OFF_W1H + ubase;
    const uint32_t a1l = sbase + OFF_W1L + ubase;
    const uint32_t a2hB = sbase + OFF_W2H + ubase;
    const uint32_t a2lB = sbase + OFF_W2L + ubase;

    // A tile reads: addr(u, v, s, w) = tOff + u*4608 + v*2304 + s*64 + w*32
    const int tOff = OFF_TILE + wid * TILE_PER_W + g * TILE_PITCH + t * 8;
    #define ATILE(u, v, s, w) \
        (*(const float2*)(smem + tOff + (u) * (16 * TILE_PITCH) + (v) * (8 * TILE_PITCH) + (s) * 64 + (w) * 32))

    const bool ok0 = (row0 + g)      < N;
    const bool ok1 = (row0 + g + 8)  < N;
    const bool ok2 = (row0 + 16 + g) < N;
    const bool ok3 = (row0 + 24 + g) < N;

    // ---- layer-1 accumulators (bias-initialized), both slabs ----
    float c1[2][8][4];
    #pragma unroll
    for (int j = 0; j < 8; ++j) {
        const float2 bj = *(const float2*)(smem + OFF_B1 + (8 * j + 2 * t) * 4);
        #pragma unroll
        for (int u = 0; u < 2; ++u) {
            c1[u][j][0] = bj.x; c1[u][j][1] = bj.y;
            c1[u][j][2] = bj.x; c1[u][j][3] = bj.y;
        }
    }

    // ---------------- Layer 1 (B fragments shared by both slabs) ----------------
    #pragma unroll
    for (int s = 0; s < 4; ++s) {
        uint32_t ah[2][4], al[2][4];
        #pragma unroll
        for (int u = 0; u < 2; ++u) {
            split2(ATILE(u, 0, s, 0), ah[u][0], al[u][0]);
            split2(ATILE(u, 1, s, 0), ah[u][1], al[u][1]);
            split2(ATILE(u, 0, s, 1), ah[u][2], al[u][2]);
            split2(ATILE(u, 1, s, 1), ah[u][3], al[u][3]);
        }

        #pragma unroll
        for (int jj = 0; jj < 4; ++jj) {
            const uint32_t off = (2048u * s + 32u * jj) ^ m56;
            uint32_t bh0, bh1, bh2, bh3, bl0, bl1, bl2, bl3;
            ldsm_x4_t(bh0, bh1, bh2, bh3, a1h + off);
            ldsm_x4_t(bl0, bl1, bl2, bl3, a1l + off);
            // D += Ahi*Bhi + Alo*Bhi + Ahi*Blo  (slab-interleaved for ILP)
            mma16816(c1[0][2 * jj],     ah[0], bh0, bh1);
            mma16816(c1[1][2 * jj],     ah[1], bh0, bh1);
            mma16816(c1[0][2 * jj + 1], ah[0], bh2, bh3);
            mma16816(c1[1][2 * jj + 1], ah[1], bh2, bh3);
            mma16816(c1[0][2 * jj],     al[0], bh0, bh1);
            mma16816(c1[1][2 * jj],     al[1], bh0, bh1);
            mma16816(c1[0][2 * jj + 1], al[0], bh2, bh3);
            mma16816(c1[1][2 * jj + 1], al[1], bh2, bh3);
            mma16816(c1[0][2 * jj],     ah[0], bl0, bl1);
            mma16816(c1[1][2 * jj],     ah[1], bl0, bl1);
            mma16816(c1[0][2 * jj + 1], ah[0], bl2, bl3);
            mma16816(c1[1][2 * jj + 1], ah[1], bl2, bl3);
        }
    }

    // ---------------- Layer 2: progressive per k-step ----------------
    float c2[2][4][4];
    #pragma unroll
    for (int j = 0; j < 4; ++j) {
        const float2 bj = *(const float2*)(smem + OFF_B2 + (8 * j + 2 * t) * 4);
        #pragma unroll
        for (int u = 0; u < 2; ++u) {
            c2[u][j][0] = bj.x; c2[u][j][1] = bj.y;
            c2[u][j][2] = bj.x; c2[u][j][3] = bj.y;
        }
    }

    #pragma unroll
    for (int s = 0; s < 4; ++s) {
        // convert c1 ntiles {2s, 2s+1} of both slabs -> A-frags for k-step s
        uint32_t a2h[2][4], a2l[2][4];
        #pragma unroll
        for (int u = 0; u < 2; ++u) {
            #pragma unroll
            for (int jl = 0; jl < 2; ++jl) {
                const int j = 2 * s + jl;
                const int o = jl << 1;              // even ntile -> a0,a1; odd -> a2,a3
                const float x0 = fmaxf(c1[u][j][0], 0.f);
                const float y0 = fmaxf(c1[u][j][1], 0.f);
                const float x1 = fmaxf(c1[u][j][2], 0.f);
                const float y1 = fmaxf(c1[u][j][3], 0.f);
                split2(make_float2(x0, y0), a2h[u][o],     a2l[u][o]);
                split2(make_float2(x1, y1), a2h[u][o + 1], a2l[u][o + 1]);
            }
        }

        #pragma unroll
        for (int jj = 0; jj < 2; ++jj) {
            const uint32_t off = (2048u * s + 32u * jj) ^ m56;
            uint32_t bh0, bh1, bh2, bh3, bl0, bl1, bl2, bl3;
            ldsm_x4_t(bh0, bh1, bh2, bh3, a2hB + off);
            ldsm_x4_t(bl0, bl1, bl2, bl3, a2lB + off);
            mma16816(c2[0][2 * jj],     a2h[0], bh0, bh1);
            mma16816(c2[1][2 * jj],     a2h[1], bh0, bh1);
            mma16816(c2[0][2 * jj + 1], a2h[0], bh2, bh3);
            mma16816(c2[1][2 * jj + 1], a2h[1], bh2, bh3);
            mma16816(c2[0][2 * jj],     a2l[0], bh0, bh1);
            mma16816(c2[1][2 * jj],     a2l[1], bh0, bh1);
            mma16816(c2[0][2 * jj + 1], a2l[0], bh2, bh3);
            mma16816(c2[1][2 * jj + 1], a2l[1], bh2, bh3);
            mma16816(c2[0][2 * jj],     a2h[0], bl0, bl1);
            mma16816(c2[1][2 * jj],     a2h[1], bl0, bl1);
            mma16816(c2[0][2 * jj + 1], a2h[0], bl2, bl3);
            mma16816(c2[1][2 * jj + 1], a2h[1], bl2, bl3);
        }
    }

    // ---- epilogue: store (float2, coalesced) ----
    #pragma unroll
    for (int j = 0; j < 4; ++j) {
        if (ok0)
            *(float2*)(out + (size_t)(row0 + g) * 32 + 8 * j + 2 * t) =
                make_float2(c2[0][j][0], c2[0][j][1]);
        if (ok1)
            *(float2*)(out + (size_t)(row0 + g + 8) * 32 + 8 * j + 2 * t) =
                make_float2(c2[0][j][2], c2[0][j][3]);
        if (ok2)
            *(float2*)(out + (size_t)(row0 + 16 + g) * 32 + 8 * j + 2 * t) =
                make_float2(c2[1][j][0], c2[1][j][1]);
        if (ok3)
            *(float2*)(out + (size_t)(row0 + 24 + g) * 32 + 8 * j + 2 * t) =
                make_float2(c2[1][j][2], c2[1][j][3]);
    }
}

extern "C" void kernel_launch(void* const* d_in, const int* in_sizes, int n_in,
                              void* d_out, int out_size)
{
    const float* h  = (const float*)d_in[0];
    const float* W1 = (const float*)d_in[1];
    const float* b1 = (const float*)d_in[2];
    const float* W2 = (const float*)d_in[3];
    const float* b2 = (const float*)d_in[4];
    float* out = (float*)d_out;

    const int N = in_sizes[0] / 64;              // 100000
    const int nPairs = (N + 31) / 32;            // 3125 (32 rows per warp)
    const int grid = (nPairs + (TPB / 32) - 1) / (TPB / 32);   // 391, 1 pair/warp

    cudaFuncSetAttribute(mlp_hmma_kernel,
                         cudaFuncAttributeMaxDynamicSharedMemorySize, SMEM_TOTAL);
    mlp_hmma_kernel<<<grid, TPB, SMEM_TOTAL>>>(h, W1, b1, W2, b2, out, N);
}

// round 12
// speedup vs baseline: 1.0015x; 1.0015x over previous
#include <cuda_runtime.h>
#include <cuda_bf16.h>
#include <cstdint>

// out = relu(h @ W1[0:64,:] + b1) @ W2[0:64,:] + b2   (edge weights hardcoded 0)
// Warp-level bf16 split-precision HMMA (mma.sync m16n8k16), fp32 accumulate.
// D = Ahi*Bhi + Ahi*Blo + Alo*Bhi. Layer-1 C-frag == layer-2 A-frag layout.
// DUAL-SLAB (32 rows/warp), 1 pair/warp, grid=391 — R9 structure verbatim,
// EXCEPT: the 16 A-row LDG.64 per lane are hoisted to kernel entry so their
// DRAM latency hides under the weight-staging phase + barrier (no new instrs).

#define TPB   256

#define SWZ(o) ((uint32_t)(o) ^ ((((uint32_t)(o)) >> 3) & 0x70))

__device__ __forceinline__ uint32_t smem_u32(const void* p) {
    uint32_t a;
    asm("{ .reg .u64 t; cvta.to.shared.u64 t, %1; cvt.u32.u64 %0, t; }" : "=r"(a) : "l"(p));
    return a;
}

__device__ __forceinline__ void ldsm_x4_t(uint32_t& r0, uint32_t& r1, uint32_t& r2, uint32_t& r3,
                                          uint32_t addr) {
    asm volatile("ldmatrix.sync.aligned.m8n8.x4.trans.shared.b16 {%0,%1,%2,%3}, [%4];"
                 : "=r"(r0), "=r"(r1), "=r"(r2), "=r"(r3) : "r"(addr));
}

__device__ __forceinline__ void mma16816(float* c, const uint32_t* a, uint32_t b0, uint32_t b1) {
    asm volatile(
        "mma.sync.aligned.m16n8k16.row.col.f32.bf16.bf16.f32 "
        "{%0,%1,%2,%3}, {%4,%5,%6,%7}, {%8,%9}, {%0,%1,%2,%3};"
        : "+f"(c[0]), "+f"(c[1]), "+f"(c[2]), "+f"(c[3])
        : "r"(a[0]), "r"(a[1]), "r"(a[2]), "r"(a[3]), "r"(b0), "r"(b1));
}

// split float2 {even k, odd k} -> packed hi bf16x2 / lo bf16x2.
__device__ __forceinline__ void split2(float2 v, uint32_t& hi, uint32_t& lo) {
    uint32_t hp;
    asm("cvt.rn.bf16x2.f32 %0, %1, %2;" : "=r"(hp) : "f"(v.y), "f"(v.x));  // lo half = v.x
    const float h0 = __uint_as_float(hp << 16);
    const float h1 = __uint_as_float(hp & 0xFFFF0000u);
    const float l0 = v.x - h0;
    const float l1 = v.y - h1;
    uint32_t lp;
    asm("cvt.rn.bf16x2.f32 %0, %1, %2;" : "=r"(lp) : "f"(l1), "f"(l0));
    hi = hp; lo = lp;
}
__device__ __forceinline__ void split4(float4 v, uint32_t& h0, uint32_t& h1,
                                       uint32_t& l0, uint32_t& l1) {
    split2(make_float2(v.x, v.y), h0, l0);
    split2(make_float2(v.z, v.w), h1, l1);
}

__global__ __launch_bounds__(TPB, 2)
void mlp_hmma_kernel(const float* __restrict__ h,
                     const float* __restrict__ W1,   // (128,64), rows 0..63 used
                     const float* __restrict__ b1,   // (64,)
                     const float* __restrict__ W2,   // (128,32), rows 0..63 used
                     const float* __restrict__ b2,   // (32,)
                     float* __restrict__ out,        // (N,32)
                     int N)
{
    // Weights: [k][n] row-major bf16, 128B pitch, SW128-swizzled. Biases fp32.
    __shared__ __align__(1024) uint8_t sW1h[64 * 128];
    __shared__ __align__(1024) uint8_t sW1l[64 * 128];
    __shared__ __align__(1024) uint8_t sW2h[64 * 128];   // 32 cols used, padded pitch
    __shared__ __align__(1024) uint8_t sW2l[64 * 128];
    __shared__ float sb1[64];
    __shared__ float sb2[32];

    const int tid = threadIdx.x;
    const int wid = tid >> 5;
    const int lid = tid & 31;

    const int pair = blockIdx.x * (TPB / 32) + wid;   // 32 rows per warp
    const int row0 = pair * 32;

    const int g = lid >> 2;        // row group 0..7
    const int t = lid & 3;         // col pair 0..3

    // ---- HOISTED A loads: issue all 16 LDG.64 before weight staging ----
    int r0 = row0 + g,      r1 = row0 + g + 8;
    int r2 = row0 + 16 + g, r3 = row0 + 24 + g;
    const bool ok0 = r0 < N, ok1 = r1 < N, ok2 = r2 < N, ok3 = r3 < N;
    if (r0 >= N) r0 = N - 1;                           // clamp loads; stores guarded
    if (r1 >= N) r1 = N - 1;
    if (r2 >= N) r2 = N - 1;
    if (r3 >= N) r3 = N - 1;
    const float2* __restrict__ p0 = (const float2*)(h + (size_t)r0 * 64);
    const float2* __restrict__ p1 = (const float2*)(h + (size_t)r1 * 64);
    const float2* __restrict__ p2 = (const float2*)(h + (size_t)r2 * 64);
    const float2* __restrict__ p3 = (const float2*)(h + (size_t)r3 * 64);

    float2 xv[4][4];   // [s][{p0@8s+t, p1@8s+t, p0@8s+4+t, p1@8s+4+t}] for slab pairing
    float2 yv[4][4];   // same for rows +16/+24 (slab 1)
    #pragma unroll
    for (int s = 0; s < 4; ++s) {
        xv[s][0] = p0[8 * s + t];
        xv[s][1] = p1[8 * s + t];
        xv[s][2] = p0[8 * s + 4 + t];
        xv[s][3] = p1[8 * s + 4 + t];
        yv[s][0] = p2[8 * s + t];
        yv[s][1] = p3[8 * s + t];
        yv[s][2] = p2[8 * s + 4 + t];
        yv[s][3] = p3[8 * s + 4 + t];
    }

    // ---- weight staging (covers the A-load latency): float4 loads, uint2 stores ----
    {
        const float4* __restrict__ W1v = (const float4*)W1;   // 1024 float4
        #pragma unroll
        for (int j = 0; j < 4; ++j) {
            const int idx = tid + j * TPB;
            const int k = idx >> 4, n4 = (idx & 15) << 2;
            uint32_t h0, h1, l0, l1; split4(W1v[idx], h0, h1, l0, l1);
            const uint32_t sw = SWZ(k * 128 + n4 * 2);
            *(uint2*)(sW1h + sw) = make_uint2(h0, h1);
            *(uint2*)(sW1l + sw) = make_uint2(l0, l1);
        }
        const float4* __restrict__ W2v = (const float4*)W2;   // 512 float4
        #pragma unroll
        for (int j = 0; j < 2; ++j) {
            const int idx = tid + j * TPB;
            const int k = idx >> 3, n4 = (idx & 7) << 2;
            uint32_t h0, h1, l0, l1; split4(W2v[idx], h0, h1, l0, l1);
            const uint32_t sw = SWZ(k * 128 + n4 * 2);
            *(uint2*)(sW2h + sw) = make_uint2(h0, h1);
            *(uint2*)(sW2l + sw) = make_uint2(l0, l1);
        }
    }
    if (tid < 64) sb1[tid] = b1[tid];
    if (tid < 32) sb2[tid] = b2[tid];
    __syncthreads();

    if (row0 >= N) return;                             // after barrier: safe

    // per-lane ldmatrix source geometry
    const int lm = lid >> 3, lr = lid & 7;
    const int kr = ((lm & 1) << 3) + lr;    // k row within 16-row k-step (0..15)
    const int nc = (lm >> 1) << 3;          // n offset within 16-col n-group (0 or 8)

    // SWZ(2048s + 128kr + 32jj + 2nc) = (u ^ (m&0x10)) + ((2048s+32jj) ^ (m&0x60))
    const uint32_t mask  = (uint32_t)((kr & 7) << 4);
    const uint32_t ubase = (uint32_t)(128 * kr + 2 * nc) ^ (mask & 0x10u);
    const uint32_t m56   = mask & 0x60u;
    const uint32_t a1h = smem_u32(sW1h) + ubase;
    const uint32_t a1l = smem_u32(sW1l) + ubase;
    const uint32_t a2hB = smem_u32(sW2h) + ubase;
    const uint32_t a2lB = smem_u32(sW2l) + ubase;

    // ---- layer-1 accumulators (bias-initialized), both slabs ----
    float c1[2][8][4];
    #pragma unroll
    for (int j = 0; j < 8; ++j) {
        const float2 bj = *(const float2*)(sb1 + 8 * j + 2 * t);
        #pragma unroll
        for (int u = 0; u < 2; ++u) {
            c1[u][j][0] = bj.x; c1[u][j][1] = bj.y;
            c1[u][j][2] = bj.x; c1[u][j][3] = bj.y;
        }
    }

    // ---------------- Layer 1 (B fragments shared by both slabs) ----------------
    #pragma unroll
    for (int s = 0; s < 4; ++s) {
        uint32_t ah[2][4], al[2][4];
        #pragma unroll
        for (int q = 0; q < 4; ++q) {
            split2(xv[s][q], ah[0][q], al[0][q]);
            split2(yv[s][q], ah[1][q], al[1][q]);
        }

        #pragma unroll
        for (int jj = 0; jj < 4; ++jj) {
            const uint32_t off = (2048u * s + 32u * jj) ^ m56;
            uint32_t bh0, bh1, bh2, bh3, bl0, bl1, bl2, bl3;
            ldsm_x4_t(bh0, bh1, bh2, bh3, a1h + off);
            ldsm_x4_t(bl0, bl1, bl2, bl3, a1l + off);
            // slab-interleaved: every same-acc chain has an independent twin
            mma16816(c1[0][2 * jj],     ah[0], bh0, bh1);
            mma16816(c1[1][2 * jj],     ah[1], bh0, bh1);
            mma16816(c1[0][2 * jj + 1], ah[0], bh2, bh3);
            mma16816(c1[1][2 * jj + 1], ah[1], bh2, bh3);
            mma16816(c1[0][2 * jj],     ah[0], bl0, bl1);
            mma16816(c1[1][2 * jj],     ah[1], bl0, bl1);
            mma16816(c1[0][2 * jj + 1], ah[0], bl2, bl3);
            mma16816(c1[1][2 * jj + 1], ah[1], bl2, bl3);
            mma16816(c1[0][2 * jj],     al[0], bh0, bh1);
            mma16816(c1[1][2 * jj],     al[1], bh0, bh1);
            mma16816(c1[0][2 * jj + 1], al[0], bh2, bh3);
            mma16816(c1[1][2 * jj + 1], al[1], bh2, bh3);
        }
    }

    // ---------------- Layer 2: progressive per k-step ----------------
    float c2[2][4][4];
    #pragma unroll
    for (int j = 0; j < 4; ++j) {
        const float2 bj = *(const float2*)(sb2 + 8 * j + 2 * t);
        #pragma unroll
        for (int u = 0; u < 2; ++u) {
            c2[u][j][0] = bj.x; c2[u][j][1] = bj.y;
            c2[u][j][2] = bj.x; c2[u][j][3] = bj.y;
        }
    }

    #pragma unroll
    for (int s = 0; s < 4; ++s) {
        // convert c1 ntiles {2s, 2s+1} of both slabs -> A-frags for k-step s
        uint32_t a2h[2][4], a2l[2][4];
        #pragma unroll
        for (int u = 0; u < 2; ++u) {
            #pragma unroll
            for (int jl = 0; jl < 2; ++jl) {
                const int j = 2 * s + jl;
                const int o = jl << 1;              // even ntile -> a0,a1; odd -> a2,a3
                const float x0 = fmaxf(c1[u][j][0], 0.f);
                const float y0 = fmaxf(c1[u][j][1], 0.f);
                const float x1 = fmaxf(c1[u][j][2], 0.f);
                const float y1 = fmaxf(c1[u][j][3], 0.f);
                split2(make_float2(x0, y0), a2h[u][o],     a2l[u][o]);
                split2(make_float2(x1, y1), a2h[u][o + 1], a2l[u][o + 1]);
            }
        }

        #pragma unroll
        for (int jj = 0; jj < 2; ++jj) {
            const uint32_t off = (2048u * s + 32u * jj) ^ m56;
            uint32_t bh0, bh1, bh2, bh3, bl0, bl1, bl2, bl3;
            ldsm_x4_t(bh0, bh1, bh2, bh3, a2hB + off);
            ldsm_x4_t(bl0, bl1, bl2, bl3, a2lB + off);
            mma16816(c2[0][2 * jj],     a2h[0], bh0, bh1);
            mma16816(c2[1][2 * jj],     a2h[1], bh0, bh1);
            mma16816(c2[0][2 * jj + 1], a2h[0], bh2, bh3);
            mma16816(c2[1][2 * jj + 1], a2h[1], bh2, bh3);
            mma16816(c2[0][2 * jj],     a2h[0], bl0, bl1);
            mma16816(c2[1][2 * jj],     a2h[1], bl0, bl1);
            mma16816(c2[0][2 * jj + 1], a2h[0], bl2, bl3);
            mma16816(c2[1][2 * jj + 1], a2h[1], bl2, bl3);
            mma16816(c2[0][2 * jj],     a2l[0], bh0, bh1);
            mma16816(c2[1][2 * jj],     a2l[1], bh0, bh1);
            mma16816(c2[0][2 * jj + 1], a2l[0], bh2, bh3);
            mma16816(c2[1][2 * jj + 1], a2l[1], bh2, bh3);
        }
    }

    // ---- epilogue: store (float2, coalesced) ----
    #pragma unroll
    for (int j = 0; j < 4; ++j) {
        if (ok0)
            *(float2*)(out + (size_t)(row0 + g) * 32 + 8 * j + 2 * t) =
                make_float2(c2[0][j][0], c2[0][j][1]);
        if (ok1)
            *(float2*)(out + (size_t)(row0 + g + 8) * 32 + 8 * j + 2 * t) =
                make_float2(c2[0][j][2], c2[0][j][3]);
        if (ok2)
            *(float2*)(out + (size_t)(row0 + 16 + g) * 32 + 8 * j + 2 * t) =
                make_float2(c2[1][j][0], c2[1][j][1]);
        if (ok3)
            *(float2*)(out + (size_t)(row0 + 24 + g) * 32 + 8 * j + 2 * t) =
                make_float2(c2[1][j][2], c2[1][j][3]);
    }
}

extern "C" void kernel_launch(void* const* d_in, const int* in_sizes, int n_in,
                              void* d_out, int out_size)
{
    const float* h  = (const float*)d_in[0];
    const float* W1 = (const float*)d_in[1];
    const float* b1 = (const float*)d_in[2];
    const float* W2 = (const float*)d_in[3];
    const float* b2 = (const float*)d_in[4];
    float* out = (float*)d_out;

    const int N = in_sizes[0] / 64;              // 100000
    const int nPairs = (N + 31) / 32;            // 3125 (32 rows per warp)
    const int grid = (nPairs + (TPB / 32) - 1) / (TPB / 32);   // 391, 1 pair/warp

    mlp_hmma_kernel<<<grid, TPB>>>(h, W1, b1, W2, b2, out, N);
}

// round 13
// speedup vs baseline: 1.1235x; 1.1218x over previous
#include <cuda_runtime.h>
#include <cuda_bf16.h>
#include <cstdint>

// out = relu(h @ W1[0:64,:] + b1) @ W2[0:64,:] + b2   (edge weights hardcoded 0)
// Warp-level bf16 split-precision HMMA (mma.sync m16n8k16), fp32 accumulate.
// D = Ahi*Bhi + Ahi*Blo + Alo*Bhi. Layer-1 C-frag == layer-2 A-frag layout.
// DUAL-SLAB (32 rows/warp), 1 pair/warp, grid=391 (R9 shape).
// N-HALVED: layer-1 n-cols processed in two halves of 32; each half's H1 ntiles
// feed their two layer-2 k-steps immediately. Live c1 drops 64->32 regs, freeing
// the register file so ptxas can batch LDSMs and run 8 MMA chains in flight.

#define TPB   256

#define SWZ(o) ((uint32_t)(o) ^ ((((uint32_t)(o)) >> 3) & 0x70))

__device__ __forceinline__ uint32_t smem_u32(const void* p) {
    uint32_t a;
    asm("{ .reg .u64 t; cvta.to.shared.u64 t, %1; cvt.u32.u64 %0, t; }" : "=r"(a) : "l"(p));
    return a;
}

__device__ __forceinline__ void ldsm_x4_t(uint32_t& r0, uint32_t& r1, uint32_t& r2, uint32_t& r3,
                                          uint32_t addr) {
    asm volatile("ldmatrix.sync.aligned.m8n8.x4.trans.shared.b16 {%0,%1,%2,%3}, [%4];"
                 : "=r"(r0), "=r"(r1), "=r"(r2), "=r"(r3) : "r"(addr));
}

__device__ __forceinline__ void mma16816(float* c, const uint32_t* a, uint32_t b0, uint32_t b1) {
    asm volatile(
        "mma.sync.aligned.m16n8k16.row.col.f32.bf16.bf16.f32 "
        "{%0,%1,%2,%3}, {%4,%5,%6,%7}, {%8,%9}, {%0,%1,%2,%3};"
        : "+f"(c[0]), "+f"(c[1]), "+f"(c[2]), "+f"(c[3])
        : "r"(a[0]), "r"(a[1]), "r"(a[2]), "r"(a[3]), "r"(b0), "r"(b1));
}

// split float2 {even k, odd k} -> packed hi bf16x2 / lo bf16x2.
__device__ __forceinline__ void split2(float2 v, uint32_t& hi, uint32_t& lo) {
    uint32_t hp;
    asm("cvt.rn.bf16x2.f32 %0, %1, %2;" : "=r"(hp) : "f"(v.y), "f"(v.x));  // lo half = v.x
    const float h0 = __uint_as_float(hp << 16);
    const float h1 = __uint_as_float(hp & 0xFFFF0000u);
    const float l0 = v.x - h0;
    const float l1 = v.y - h1;
    uint32_t lp;
    asm("cvt.rn.bf16x2.f32 %0, %1, %2;" : "=r"(lp) : "f"(l1), "f"(l0));
    hi = hp; lo = lp;
}
__device__ __forceinline__ void split4(float4 v, uint32_t& h0, uint32_t& h1,
                                       uint32_t& l0, uint32_t& l1) {
    split2(make_float2(v.x, v.y), h0, l0);
    split2(make_float2(v.z, v.w), h1, l1);
}

__global__ __launch_bounds__(TPB, 2)
void mlp_hmma_kernel(const float* __restrict__ h,
                     const float* __restrict__ W1,   // (128,64), rows 0..63 used
                     const float* __restrict__ b1,   // (64,)
                     const float* __restrict__ W2,   // (128,32), rows 0..63 used
                     const float* __restrict__ b2,   // (32,)
                     float* __restrict__ out,        // (N,32)
                     int N)
{
    // Weights: [k][n] row-major bf16, 128B pitch, SW128-swizzled. Biases fp32.
    __shared__ __align__(1024) uint8_t sW1h[64 * 128];
    __shared__ __align__(1024) uint8_t sW1l[64 * 128];
    __shared__ __align__(1024) uint8_t sW2h[64 * 128];   // 32 cols used, padded pitch
    __shared__ __align__(1024) uint8_t sW2l[64 * 128];
    __shared__ float sb1[64];
    __shared__ float sb2[32];

    const int tid = threadIdx.x;
    const int wid = tid >> 5;
    const int lid = tid & 31;

    // ---- vectorized weight staging: float4 loads, uint2 swizzled stores ----
    {
        const float4* __restrict__ W1v = (const float4*)W1;   // 1024 float4
        #pragma unroll
        for (int j = 0; j < 4; ++j) {
            const int idx = tid + j * TPB;
            const int k = idx >> 4, n4 = (idx & 15) << 2;
            uint32_t h0, h1, l0, l1; split4(W1v[idx], h0, h1, l0, l1);
            const uint32_t sw = SWZ(k * 128 + n4 * 2);
            *(uint2*)(sW1h + sw) = make_uint2(h0, h1);
            *(uint2*)(sW1l + sw) = make_uint2(l0, l1);
        }
        const float4* __restrict__ W2v = (const float4*)W2;   // 512 float4
        #pragma unroll
        for (int j = 0; j < 2; ++j) {
            const int idx = tid + j * TPB;
            const int k = idx >> 3, n4 = (idx & 7) << 2;
            uint32_t h0, h1, l0, l1; split4(W2v[idx], h0, h1, l0, l1);
            const uint32_t sw = SWZ(k * 128 + n4 * 2);
            *(uint2*)(sW2h + sw) = make_uint2(h0, h1);
            *(uint2*)(sW2l + sw) = make_uint2(l0, l1);
        }
    }
    if (tid < 64) sb1[tid] = b1[tid];
    if (tid < 32) sb2[tid] = b2[tid];
    __syncthreads();

    const int pair = blockIdx.x * (TPB / 32) + wid;   // 32 rows per warp
    const int row0 = pair * 32;
    if (row0 >= N) return;

    const int g = lid >> 2;        // row group 0..7
    const int t = lid & 3;         // col pair 0..3

    // per-lane ldmatrix source geometry
    const int lm = lid >> 3, lr = lid & 7;
    const int kr = ((lm & 1) << 3) + lr;    // k row within 16-row k-step (0..15)
    const int nc = (lm >> 1) << 3;          // n offset within 16-col n-group (0 or 8)

    // SWZ(2048s + 128kr + 32jj + 2nc) = (u ^ (m&0x10)) + ((2048s+32jj) ^ (m&0x60))
    const uint32_t mask  = (uint32_t)((kr & 7) << 4);
    const uint32_t ubase = (uint32_t)(128 * kr + 2 * nc) ^ (mask & 0x10u);
    const uint32_t m56   = mask & 0x60u;
    const uint32_t a1h = smem_u32(sW1h) + ubase;
    const uint32_t a1l = smem_u32(sW1l) + ubase;
    const uint32_t a2hB = smem_u32(sW2h) + ubase;
    const uint32_t a2lB = smem_u32(sW2l) + ubase;

    // ---- A rows (fp32, live through both halves: 32 regs) ----
    int r0 = row0 + g,      r1 = row0 + g + 8;
    int r2 = row0 + 16 + g, r3 = row0 + 24 + g;
    const bool ok0 = r0 < N, ok1 = r1 < N, ok2 = r2 < N, ok3 = r3 < N;
    if (r0 >= N) r0 = N - 1;               // clamp loads; stores guarded
    if (r1 >= N) r1 = N - 1;
    if (r2 >= N) r2 = N - 1;
    if (r3 >= N) r3 = N - 1;
    const float2* __restrict__ p0 = (const float2*)(h + (size_t)r0 * 64);
    const float2* __restrict__ p1 = (const float2*)(h + (size_t)r1 * 64);
    const float2* __restrict__ p2 = (const float2*)(h + (size_t)r2 * 64);
    const float2* __restrict__ p3 = (const float2*)(h + (size_t)r3 * 64);

    float2 xv[4][4], yv[4][4];             // [s][frag]: slab0, slab1
    #pragma unroll
    for (int s = 0; s < 4; ++s) {
        xv[s][0] = p0[8 * s + t];
        xv[s][1] = p1[8 * s + t];
        xv[s][2] = p0[8 * s + 4 + t];
        xv[s][3] = p1[8 * s + 4 + t];
        yv[s][0] = p2[8 * s + t];
        yv[s][1] = p3[8 * s + t];
        yv[s][2] = p2[8 * s + 4 + t];
        yv[s][3] = p3[8 * s + 4 + t];
    }

    float c2[2][4][4];                     // layer-2 accumulators (init at interlude 0)

    #pragma unroll
    for (int half = 0; half < 2; ++half) {
        // ---- layer-1 accumulators for this n-half (32 regs), bias-initialized ----
        float c1h[2][4][4];                // local ntile jl 0..3 = global ntile 4*half+jl
        #pragma unroll
        for (int jl = 0; jl < 4; ++jl) {
            const float2 bj = *(const float2*)(sb1 + 8 * (4 * half + jl) + 2 * t);
            #pragma unroll
            for (int u = 0; u < 2; ++u) {
                c1h[u][jl][0] = bj.x; c1h[u][jl][1] = bj.y;
                c1h[u][jl][2] = bj.x; c1h[u][jl][3] = bj.y;
            }
        }

        // ---- layer 1, this half: full K, n-cols [32*half, 32*half+32) ----
        #pragma unroll
        for (int s = 0; s < 4; ++s) {
            uint32_t ah[2][4], al[2][4];
            #pragma unroll
            for (int q = 0; q < 4; ++q) {
                split2(xv[s][q], ah[0][q], al[0][q]);
                split2(yv[s][q], ah[1][q], al[1][q]);
            }

            #pragma unroll
            for (int j2 = 0; j2 < 2; ++j2) {           // global jj = 2*half + j2
                const uint32_t off = (2048u * s + 32u * (2 * half + j2)) ^ m56;
                uint32_t bh0, bh1, bh2, bh3, bl0, bl1, bl2, bl3;
                ldsm_x4_t(bh0, bh1, bh2, bh3, a1h + off);
                ldsm_x4_t(bl0, bl1, bl2, bl3, a1l + off);
                mma16816(c1h[0][2 * j2],     ah[0], bh0, bh1);
                mma16816(c1h[1][2 * j2],     ah[1], bh0, bh1);
                mma16816(c1h[0][2 * j2 + 1], ah[0], bh2, bh3);
                mma16816(c1h[1][2 * j2 + 1], ah[1], bh2, bh3);
                mma16816(c1h[0][2 * j2],     ah[0], bl0, bl1);
                mma16816(c1h[1][2 * j2],     ah[1], bl0, bl1);
                mma16816(c1h[0][2 * j2 + 1], ah[0], bl2, bl3);
                mma16816(c1h[1][2 * j2 + 1], ah[1], bl2, bl3);
                mma16816(c1h[0][2 * j2],     al[0], bh0, bh1);
                mma16816(c1h[1][2 * j2],     al[1], bh0, bh1);
                mma16816(c1h[0][2 * j2 + 1], al[0], bh2, bh3);
                mma16816(c1h[1][2 * j2 + 1], al[1], bh2, bh3);
            }
        }

        // ---- c2 init at the first interlude (keeps it out of phase-A pressure) ----
        if (half == 0) {
            #pragma unroll
            for (int j = 0; j < 4; ++j) {
                const float2 bj = *(const float2*)(sb2 + 8 * j + 2 * t);
                #pragma unroll
                for (int u = 0; u < 2; ++u) {
                    c2[u][j][0] = bj.x; c2[u][j][1] = bj.y;
                    c2[u][j][2] = bj.x; c2[u][j][3] = bj.y;
                }
            }
        }

        // ---- layer 2, k-steps 2*half and 2*half+1 (from this half's H1 ntiles) ----
        #pragma unroll
        for (int s2l = 0; s2l < 2; ++s2l) {            // global k-step = 2*half + s2l
            uint32_t a2h[2][4], a2l[2][4];
            #pragma unroll
            for (int u = 0; u < 2; ++u) {
                #pragma unroll
                for (int jl2 = 0; jl2 < 2; ++jl2) {
                    const int jl = 2 * s2l + jl2;      // local ntile
                    const int o = jl2 << 1;            // even ntile -> a0,a1; odd -> a2,a3
                    const float x0 = fmaxf(c1h[u][jl][0], 0.f);
                    const float y0 = fmaxf(c1h[u][jl][1], 0.f);
                    const float x1 = fmaxf(c1h[u][jl][2], 0.f);
                    const float y1 = fmaxf(c1h[u][jl][3], 0.f);
                    split2(make_float2(x0, y0), a2h[u][o],     a2l[u][o]);
                    split2(make_float2(x1, y1), a2h[u][o + 1], a2l[u][o + 1]);
                }
            }

            #pragma unroll
            for (int jj = 0; jj < 2; ++jj) {
                const uint32_t off = (2048u * (2 * half + s2l) + 32u * jj) ^ m56;
                uint32_t bh0, bh1, bh2, bh3, bl0, bl1, bl2, bl3;
                ldsm_x4_t(bh0, bh1, bh2, bh3, a2hB + off);
                ldsm_x4_t(bl0, bl1, bl2, bl3, a2lB + off);
                mma16816(c2[0][2 * jj],     a2h[0], bh0, bh1);
                mma16816(c2[1][2 * jj],     a2h[1], bh0, bh1);
                mma16816(c2[0][2 * jj + 1], a2h[0], bh2, bh3);
                mma16816(c2[1][2 * jj + 1], a2h[1], bh2, bh3);
                mma16816(c2[0][2 * jj],     a2h[0], bl0, bl1);
                mma16816(c2[1][2 * jj],     a2h[1], bl0, bl1);
                mma16816(c2[0][2 * jj + 1], a2h[0], bl2, bl3);
                mma16816(c2[1][2 * jj + 1], a2h[1], bl2, bl3);
                mma16816(c2[0][2 * jj],     a2l[0], bh0, bh1);
                mma16816(c2[1][2 * jj],     a2l[1], bh0, bh1);
                mma16816(c2[0][2 * jj + 1], a2l[0], bh2, bh3);
                mma16816(c2[1][2 * jj + 1], a2l[1], bh2, bh3);
            }
        }
    }

    // ---- epilogue: store (float2, coalesced) ----
    #pragma unroll
    for (int j = 0; j < 4; ++j) {
        if (ok0)
            *(float2*)(out + (size_t)(row0 + g) * 32 + 8 * j + 2 * t) =
                make_float2(c2[0][j][0], c2[0][j][1]);
        if (ok1)
            *(float2*)(out + (size_t)(row0 + g + 8) * 32 + 8 * j + 2 * t) =
                make_float2(c2[0][j][2], c2[0][j][3]);
        if (ok2)
            *(float2*)(out + (size_t)(row0 + 16 + g) * 32 + 8 * j + 2 * t) =
                make_float2(c2[1][j][0], c2[1][j][1]);
        if (ok3)
            *(float2*)(out + (size_t)(row0 + 24 + g) * 32 + 8 * j + 2 * t) =
                make_float2(c2[1][j][2], c2[1][j][3]);
    }
}

extern "C" void kernel_launch(void* const* d_in, const int* in_sizes, int n_in,
                              void* d_out, int out_size)
{
    const float* h  = (const float*)d_in[0];
    const float* W1 = (const float*)d_in[1];
    const float* b1 = (const float*)d_in[2];
    const float* W2 = (const float*)d_in[3];
    const float* b2 = (const float*)d_in[4];
    float* out = (float*)d_out;

    const int N = in_sizes[0] / 64;              // 100000
    const int nPairs = (N + 31) / 32;            // 3125 (32 rows per warp)
    const int grid = (nPairs + (TPB / 32) - 1) / (TPB / 32);   // 391, 1 pair/warp

    mlp_hmma_kernel<<<grid, TPB>>>(h, W1, b1, W2, b2, out, N);
}

// round 14
// speedup vs baseline: 1.2552x; 1.1172x over previous
#include <cuda_runtime.h>
#include <cuda_bf16.h>
#include <cstdint>

// out = relu(h @ W1[0:64,:] + b1) @ W2[0:64,:] + b2   (edge weights hardcoded 0)
// Warp-level bf16 split-precision HMMA (mma.sync m16n8k16), fp32 accumulate.
// D = Ahi*Bhi + Ahi*Blo + Alo*Bhi. Layer-1 C-frag == layer-2 A-frag layout.
// DUAL-SLAB (32 rows/warp), 1 pair/warp, grid=391 — Round-9 structure (best
// measured: 16.9us). FULL template param drops row guards/clamps when N%32==0
// (true for the bench shape: N=100000 -> 3125 exact pairs).

#define TPB   256

#define SWZ(o) ((uint32_t)(o) ^ ((((uint32_t)(o)) >> 3) & 0x70))

__device__ __forceinline__ uint32_t smem_u32(const void* p) {
    uint32_t a;
    asm("{ .reg .u64 t; cvta.to.shared.u64 t, %1; cvt.u32.u64 %0, t; }" : "=r"(a) : "l"(p));
    return a;
}

__device__ __forceinline__ void ldsm_x4_t(uint32_t& r0, uint32_t& r1, uint32_t& r2, uint32_t& r3,
                                          uint32_t addr) {
    asm volatile("ldmatrix.sync.aligned.m8n8.x4.trans.shared.b16 {%0,%1,%2,%3}, [%4];"
                 : "=r"(r0), "=r"(r1), "=r"(r2), "=r"(r3) : "r"(addr));
}

__device__ __forceinline__ void mma16816(float* c, const uint32_t* a, uint32_t b0, uint32_t b1) {
    asm volatile(
        "mma.sync.aligned.m16n8k16.row.col.f32.bf16.bf16.f32 "
        "{%0,%1,%2,%3}, {%4,%5,%6,%7}, {%8,%9}, {%0,%1,%2,%3};"
        : "+f"(c[0]), "+f"(c[1]), "+f"(c[2]), "+f"(c[3])
        : "r"(a[0]), "r"(a[1]), "r"(a[2]), "r"(a[3]), "r"(b0), "r"(b1));
}

// split float2 {even k, odd k} -> packed hi bf16x2 / lo bf16x2.
__device__ __forceinline__ void split2(float2 v, uint32_t& hi, uint32_t& lo) {
    uint32_t hp;
    asm("cvt.rn.bf16x2.f32 %0, %1, %2;" : "=r"(hp) : "f"(v.y), "f"(v.x));  // lo half = v.x
    const float h0 = __uint_as_float(hp << 16);
    const float h1 = __uint_as_float(hp & 0xFFFF0000u);
    const float l0 = v.x - h0;
    const float l1 = v.y - h1;
    uint32_t lp;
    asm("cvt.rn.bf16x2.f32 %0, %1, %2;" : "=r"(lp) : "f"(l1), "f"(l0));
    hi = hp; lo = lp;
}
__device__ __forceinline__ void split4(float4 v, uint32_t& h0, uint32_t& h1,
                                       uint32_t& l0, uint32_t& l1) {
    split2(make_float2(v.x, v.y), h0, l0);
    split2(make_float2(v.z, v.w), h1, l1);
}

template <bool FULL>
__global__ __launch_bounds__(TPB, 2)
void mlp_hmma_kernel(const float* __restrict__ h,
                     const float* __restrict__ W1,   // (128,64), rows 0..63 used
                     const float* __restrict__ b1,   // (64,)
                     const float* __restrict__ W2,   // (128,32), rows 0..63 used
                     const float* __restrict__ b2,   // (32,)
                     float* __restrict__ out,        // (N,32)
                     int N)
{
    // Weights: [k][n] row-major bf16, 128B pitch, SW128-swizzled. Biases fp32.
    __shared__ __align__(1024) uint8_t sW1h[64 * 128];
    __shared__ __align__(1024) uint8_t sW1l[64 * 128];
    __shared__ __align__(1024) uint8_t sW2h[64 * 128];   // 32 cols used, padded pitch
    __shared__ __align__(1024) uint8_t sW2l[64 * 128];
    __shared__ float sb1[64];
    __shared__ float sb2[32];

    const int tid = threadIdx.x;
    const int wid = tid >> 5;
    const int lid = tid & 31;

    // ---- vectorized weight staging: float4 loads, uint2 swizzled stores ----
    {
        const float4* __restrict__ W1v = (const float4*)W1;   // 1024 float4
        #pragma unroll
        for (int j = 0; j < 4; ++j) {
            const int idx = tid + j * TPB;
            const int k = idx >> 4, n4 = (idx & 15) << 2;
            uint32_t h0, h1, l0, l1; split4(W1v[idx], h0, h1, l0, l1);
            const uint32_t sw = SWZ(k * 128 + n4 * 2);
            *(uint2*)(sW1h + sw) = make_uint2(h0, h1);
            *(uint2*)(sW1l + sw) = make_uint2(l0, l1);
        }
        const float4* __restrict__ W2v = (const float4*)W2;   // 512 float4
        #pragma unroll
        for (int j = 0; j < 2; ++j) {
            const int idx = tid + j * TPB;
            const int k = idx >> 3, n4 = (idx & 7) << 2;
            uint32_t h0, h1, l0, l1; split4(W2v[idx], h0, h1, l0, l1);
            const uint32_t sw = SWZ(k * 128 + n4 * 2);
            *(uint2*)(sW2h + sw) = make_uint2(h0, h1);
            *(uint2*)(sW2l + sw) = make_uint2(l0, l1);
        }
    }
    if (tid < 64) sb1[tid] = b1[tid];
    if (tid < 32) sb2[tid] = b2[tid];
    __syncthreads();

    const int pair = blockIdx.x * (TPB / 32) + wid;   // 32 rows per warp
    const int row0 = pair * 32;
    if (row0 >= N) return;

    const int g = lid >> 2;        // row group 0..7
    const int t = lid & 3;         // col pair 0..3

    // per-lane ldmatrix source geometry
    const int lm = lid >> 3, lr = lid & 7;
    const int kr = ((lm & 1) << 3) + lr;    // k row within 16-row k-step (0..15)
    const int nc = (lm >> 1) << 3;          // n offset within 16-col n-group (0 or 8)

    // SWZ(2048s + 128kr + 32jj + 2nc) = (u ^ (m&0x10)) + ((2048s+32jj) ^ (m&0x60))
    const uint32_t mask  = (uint32_t)((kr & 7) << 4);
    const uint32_t ubase = (uint32_t)(128 * kr + 2 * nc) ^ (mask & 0x10u);
    const uint32_t m56   = mask & 0x60u;
    const uint32_t a1h = smem_u32(sW1h) + ubase;
    const uint32_t a1l = smem_u32(sW1l) + ubase;
    const uint32_t a2hB = smem_u32(sW2h) + ubase;
    const uint32_t a2lB = smem_u32(sW2l) + ubase;

    // rows: slab u covers row0+16u .. row0+16u+15; fragment rows g / g+8
    int r0 = row0 + g,      r1 = row0 + g + 8;
    int r2 = row0 + 16 + g, r3 = row0 + 24 + g;
    bool ok0 = true, ok1 = true, ok2 = true, ok3 = true;
    if (!FULL) {
        ok0 = r0 < N; ok1 = r1 < N; ok2 = r2 < N; ok3 = r3 < N;
        if (r0 >= N) r0 = N - 1;           // clamp loads; stores guarded
        if (r1 >= N) r1 = N - 1;
        if (r2 >= N) r2 = N - 1;
        if (r3 >= N) r3 = N - 1;
    }
    const float2* __restrict__ p0 = (const float2*)(h + (size_t)r0 * 64);
    const float2* __restrict__ p1 = (const float2*)(h + (size_t)r1 * 64);
    const float2* __restrict__ p2 = (const float2*)(h + (size_t)r2 * 64);
    const float2* __restrict__ p3 = (const float2*)(h + (size_t)r3 * 64);

    // ---- layer-1 accumulators (bias-initialized), both slabs ----
    float c1[2][8][4];
    #pragma unroll
    for (int j = 0; j < 8; ++j) {
        const float2 bj = *(const float2*)(sb1 + 8 * j + 2 * t);
        #pragma unroll
        for (int u = 0; u < 2; ++u) {
            c1[u][j][0] = bj.x; c1[u][j][1] = bj.y;
            c1[u][j][2] = bj.x; c1[u][j][3] = bj.y;
        }
    }

    // ---------------- Layer 1 (B fragments shared by both slabs) ----------------
    #pragma unroll
    for (int s = 0; s < 4; ++s) {
        uint32_t ah[2][4], al[2][4];
        split2(p0[8 * s + t],     ah[0][0], al[0][0]);
        split2(p1[8 * s + t],     ah[0][1], al[0][1]);
        split2(p0[8 * s + 4 + t], ah[0][2], al[0][2]);
        split2(p1[8 * s + 4 + t], ah[0][3], al[0][3]);
        split2(p2[8 * s + t],     ah[1][0], al[1][0]);
        split2(p3[8 * s + t],     ah[1][1], al[1][1]);
        split2(p2[8 * s + 4 + t], ah[1][2], al[1][2]);
        split2(p3[8 * s + 4 + t], ah[1][3], al[1][3]);

        #pragma unroll
        for (int jj = 0; jj < 4; ++jj) {
            const uint32_t off = (2048u * s + 32u * jj) ^ m56;
            uint32_t bh0, bh1, bh2, bh3, bl0, bl1, bl2, bl3;
            ldsm_x4_t(bh0, bh1, bh2, bh3, a1h + off);
            ldsm_x4_t(bl0, bl1, bl2, bl3, a1l + off);
            // slab-interleaved: every same-acc chain has an independent twin
            mma16816(c1[0][2 * jj],     ah[0], bh0, bh1);
            mma16816(c1[1][2 * jj],     ah[1], bh0, bh1);
            mma16816(c1[0][2 * jj + 1], ah[0], bh2, bh3);
            mma16816(c1[1][2 * jj + 1], ah[1], bh2, bh3);
            mma16816(c1[0][2 * jj],     ah[0], bl0, bl1);
            mma16816(c1[1][2 * jj],     ah[1], bl0, bl1);
            mma16816(c1[0][2 * jj + 1], ah[0], bl2, bl3);
            mma16816(c1[1][2 * jj + 1], ah[1], bl2, bl3);
            mma16816(c1[0][2 * jj],     al[0], bh0, bh1);
            mma16816(c1[1][2 * jj],     al[1], bh0, bh1);
            mma16816(c1[0][2 * jj + 1], al[0], bh2, bh3);
            mma16816(c1[1][2 * jj + 1], al[1], bh2, bh3);
        }
    }

    // ---------------- Layer 2: progressive per k-step ----------------
    float c2[2][4][4];
    #pragma unroll
    for (int j = 0; j < 4; ++j) {
        const float2 bj = *(const float2*)(sb2 + 8 * j + 2 * t);
        #pragma unroll
        for (int u = 0; u < 2; ++u) {
            c2[u][j][0] = bj.x; c2[u][j][1] = bj.y;
            c2[u][j][2] = bj.x; c2[u][j][3] = bj.y;
        }
    }

    #pragma unroll
    for (int s = 0; s < 4; ++s) {
        // convert c1 ntiles {2s, 2s+1} of both slabs -> A-frags for k-step s
        uint32_t a2h[2][4], a2l[2][4];
        #pragma unroll
        for (int u = 0; u < 2; ++u) {
            #pragma unroll
            for (int jl = 0; jl < 2; ++jl) {
                const int j = 2 * s + jl;
                const int o = jl << 1;              // even ntile -> a0,a1; odd -> a2,a3
                const float x0 = fmaxf(c1[u][j][0], 0.f);
                const float y0 = fmaxf(c1[u][j][1], 0.f);
                const float x1 = fmaxf(c1[u][j][2], 0.f);
                const float y1 = fmaxf(c1[u][j][3], 0.f);
                split2(make_float2(x0, y0), a2h[u][o],     a2l[u][o]);
                split2(make_float2(x1, y1), a2h[u][o + 1], a2l[u][o + 1]);
            }
        }

        #pragma unroll
        for (int jj = 0; jj < 2; ++jj) {
            const uint32_t off = (2048u * s + 32u * jj) ^ m56;
            uint32_t bh0, bh1, bh2, bh3, bl0, bl1, bl2, bl3;
            ldsm_x4_t(bh0, bh1, bh2, bh3, a2hB + off);
            ldsm_x4_t(bl0, bl1, bl2, bl3, a2lB + off);
            mma16816(c2[0][2 * jj],     a2h[0], bh0, bh1);
            mma16816(c2[1][2 * jj],     a2h[1], bh0, bh1);
            mma16816(c2[0][2 * jj + 1], a2h[0], bh2, bh3);
            mma16816(c2[1][2 * jj + 1], a2h[1], bh2, bh3);
            mma16816(c2[0][2 * jj],     a2h[0], bl0, bl1);
            mma16816(c2[1][2 * jj],     a2h[1], bl0, bl1);
            mma16816(c2[0][2 * jj + 1], a2h[0], bl2, bl3);
            mma16816(c2[1][2 * jj + 1], a2h[1], bl2, bl3);
            mma16816(c2[0][2 * jj],     a2l[0], bh0, bh1);
            mma16816(c2[1][2 * jj],     a2l[1], bh0, bh1);
            mma16816(c2[0][2 * jj + 1], a2l[0], bh2, bh3);
            mma16816(c2[1][2 * jj + 1], a2l[1], bh2, bh3);
        }
    }

    // ---- epilogue: store (float2, coalesced; unguarded when FULL) ----
    #pragma unroll
    for (int j = 0; j < 4; ++j) {
        if (ok0)
            *(float2*)(out + (size_t)(row0 + g) * 32 + 8 * j + 2 * t) =
                make_float2(c2[0][j][0], c2[0][j][1]);
        if (ok1)
            *(float2*)(out + (size_t)(row0 + g + 8) * 32 + 8 * j + 2 * t) =
                make_float2(c2[0][j][2], c2[0][j][3]);
        if (ok2)
            *(float2*)(out + (size_t)(row0 + 16 + g) * 32 + 8 * j + 2 * t) =
                make_float2(c2[1][j][0], c2[1][j][1]);
        if (ok3)
            *(float2*)(out + (size_t)(row0 + 24 + g) * 32 + 8 * j + 2 * t) =
                make_float2(c2[1][j][2], c2[1][j][3]);
    }
}

extern "C" void kernel_launch(void* const* d_in, const int* in_sizes, int n_in,
                              void* d_out, int out_size)
{
    const float* h  = (const float*)d_in[0];
    const float* W1 = (const float*)d_in[1];
    const float* b1 = (const float*)d_in[2];
    const float* W2 = (const float*)d_in[3];
    const float* b2 = (const float*)d_in[4];
    float* out = (float*)d_out;

    const int N = in_sizes[0] / 64;              // 100000
    const int nPairs = (N + 31) / 32;            // 3125 (32 rows per warp)
    const int grid = (nPairs + (TPB / 32) - 1) / (TPB / 32);   // 391, 1 pair/warp

    if (N % 32 == 0)
        mlp_hmma_kernel<true><<<grid, TPB>>>(h, W1, b1, W2, b2, out, N);
    else
        mlp_hmma_kernel<false><<<grid, TPB>>>(h, W1, b1, W2, b2, out, N);
}